// round 1
// baseline (speedup 1.0000x reference)
#include <cuda_runtime.h>
#include <cuda_bf16.h>
#include <math.h>

// ---------------- problem constants ----------------
#define DD    768
#define SS    1024
#define BB    4
#define LL    12
#define HH    12
#define HSZ   64
#define VV    32000
#define MR    (BB*SS)        // 4096 rows
#define QKVN  (3*DD)         // 2304
#define FF1   (4*DD)         // 3072
#define FF2   (3*DD)         // 2304
#define INV_SQRT_D 0.03608439182435161f   // 1/sqrt(768)
#define INV_SQRT_HS 0.125f                // 1/sqrt(64)

// ---------------- scratch (device globals; no allocs) ----------------
__device__ float g_x   [MR*DD];
__device__ float g_h   [MR*DD];
__device__ float g_qkv [MR*QKVN];
__device__ float g_o   [MR*DD];
__device__ float g_f1  [MR*FF1];
__device__ float g_f2  [MR*FF2];
__device__ float g_Wqkv[LL*DD*QKVN];
__device__ float g_bqkv[LL*QKVN];
__device__ float g_loss_sum;

// ---------------- helpers ----------------
__device__ __forceinline__ float gelu_exact(float v) {
    return 0.5f * v * (1.0f + erff(v * 0.70710678118654752f));
}

// ---------------- weight packing: Wq/Wk/Wv -> [L][D][3*D] ----------------
__global__ void pack_qkv_w(const float* __restrict__ Wq, const float* __restrict__ Wk,
                           const float* __restrict__ Wv, float* __restrict__ Wp) {
    long i = (long)blockIdx.x * blockDim.x + threadIdx.x;
    long total = (long)LL * DD * QKVN;
    if (i >= total) return;
    int c = (int)(i % QKVN);
    long rem = i / QKVN;
    int d = (int)(rem % DD);
    int l = (int)(rem / DD);
    int which = c / DD;          // 0=q,1=k,2=v
    int ce = c % DD;
    int h = ce / HSZ;
    int e = ce % HSZ;
    const float* W = (which == 0) ? Wq : (which == 1) ? Wk : Wv;
    Wp[i] = W[(((long)l*HH + h)*DD + d)*HSZ + e];
}

__global__ void pack_qkv_b(const float* __restrict__ bq, const float* __restrict__ bk,
                           const float* __restrict__ bv, float* __restrict__ bp) {
    int i = blockIdx.x * blockDim.x + threadIdx.x;
    if (i >= LL*QKVN) return;
    int c = i % QKVN;
    int l = i / QKVN;
    int which = c / DD;
    int ce = c % DD;
    int h = ce / HSZ;
    int e = ce % HSZ;
    const float* b = (which == 0) ? bq : (which == 1) ? bk : bv;
    bp[i] = b[((long)l*HH + h)*HSZ + e];
}

// ---------------- embedding ----------------
__global__ void embed_k(const int* __restrict__ idx, const float* __restrict__ tok,
                        const float* __restrict__ pos, float* __restrict__ x) {
    long i = (long)blockIdx.x * blockDim.x + threadIdx.x;
    if (i >= (long)MR*DD) return;
    int d = (int)(i % DD);
    int r = (int)(i / DD);
    int s = r & (SS - 1);
    x[i] = tok[(long)idx[r]*DD + d] + pos[(long)s*DD + d] * INV_SQRT_D;
}

// ---------------- layernorm (one block per row) ----------------
__global__ __launch_bounds__(256)
void layernorm_k(const float* __restrict__ in, float* __restrict__ out,
                 const float* __restrict__ gamma, const float* __restrict__ beta) {
    int row = blockIdx.x;
    int tid = threadIdx.x;
    const float* xr = in + (long)row*DD;
    float v0 = xr[tid], v1 = xr[tid+256], v2 = xr[tid+512];
    float s = v0+v1+v2;
    float q = v0*v0 + v1*v1 + v2*v2;
    __shared__ float sm[16];
    #pragma unroll
    for (int off = 16; off > 0; off >>= 1) {
        s += __shfl_xor_sync(0xffffffffu, s, off);
        q += __shfl_xor_sync(0xffffffffu, q, off);
    }
    int warp = tid >> 5, lane = tid & 31;
    if (lane == 0) { sm[warp] = s; sm[warp+8] = q; }
    __syncthreads();
    if (tid < 32) {
        float ss = (lane < 8) ? sm[lane] : 0.f;
        float qq = (lane < 8) ? sm[lane+8] : 0.f;
        #pragma unroll
        for (int off = 4; off > 0; off >>= 1) {
            ss += __shfl_xor_sync(0xffffffffu, ss, off);
            qq += __shfl_xor_sync(0xffffffffu, qq, off);
        }
        if (lane == 0) {
            float mu = ss * (1.0f/768.0f);
            float var = qq * (1.0f/768.0f) - mu*mu;
            sm[0] = mu;
            sm[1] = rsqrtf(var + 1e-5f);
        }
    }
    __syncthreads();
    float mu = sm[0], rs = sm[1];
    float* orow = out + (long)row*DD;
    orow[tid    ] = (v0-mu)*rs*gamma[tid    ] + beta[tid    ];
    orow[tid+256] = (v1-mu)*rs*gamma[tid+256] + beta[tid+256];
    orow[tid+512] = (v2-mu)*rs*gamma[tid+512] + beta[tid+512];
}

// ---------------- SGEMM: 128x128x16, 256 threads, 8x8 per thread ----------------
// EPI: 0 = +bias ; 1 = gelu(+bias) ; 2 = resid + scale*(acc+bias) ; 3 = plain
// TRB: B given as [N,K] row-major (compute A @ B^T)
template<int EPI, bool TRB>
__global__ __launch_bounds__(256, 2)
void sgemm_k(const float* __restrict__ A, const float* __restrict__ Bm,
             const float* __restrict__ bias, float* __restrict__ C,
             const float* __restrict__ resid, const float* __restrict__ scale_p,
             int M, int N, int K) {
    __shared__ float As[16][128];
    __shared__ float Bs[16][128];
    const int tid = threadIdx.x;
    const int bm = blockIdx.y, bn = blockIdx.x;
    const int arow = tid >> 2;          // 0..63
    const int acol = (tid & 3) * 4;     // 0,4,8,12
    const int brow = tid >> 5;          // 0..7
    const int bcol = (tid & 31) * 4;    // 0..124
    const int tr = tid >> 4, tc = tid & 15;

    float acc[8][8];
    #pragma unroll
    for (int i = 0; i < 8; i++)
        #pragma unroll
        for (int j = 0; j < 8; j++) acc[i][j] = 0.f;

    for (int k0 = 0; k0 < K; k0 += 16) {
        #pragma unroll
        for (int p = 0; p < 2; p++) {
            float4 a = *(const float4*)(A + (long)(bm*128 + arow + p*64)*K + k0 + acol);
            As[acol+0][arow+p*64] = a.x;
            As[acol+1][arow+p*64] = a.y;
            As[acol+2][arow+p*64] = a.z;
            As[acol+3][arow+p*64] = a.w;
        }
        if (TRB) {
            #pragma unroll
            for (int p = 0; p < 2; p++) {
                float4 b = *(const float4*)(Bm + (long)(bn*128 + arow + p*64)*K + k0 + acol);
                Bs[acol+0][arow+p*64] = b.x;
                Bs[acol+1][arow+p*64] = b.y;
                Bs[acol+2][arow+p*64] = b.z;
                Bs[acol+3][arow+p*64] = b.w;
            }
        } else {
            #pragma unroll
            for (int p = 0; p < 2; p++) {
                float4 b = *(const float4*)(Bm + (long)(k0 + brow + p*8)*N + bn*128 + bcol);
                *(float4*)&Bs[brow+p*8][bcol] = b;
            }
        }
        __syncthreads();
        #pragma unroll
        for (int kk = 0; kk < 16; kk++) {
            float ar[8], br[8];
            *(float4*)&ar[0] = *(const float4*)&As[kk][tr*8];
            *(float4*)&ar[4] = *(const float4*)&As[kk][tr*8+4];
            *(float4*)&br[0] = *(const float4*)&Bs[kk][tc*8];
            *(float4*)&br[4] = *(const float4*)&Bs[kk][tc*8+4];
            #pragma unroll
            for (int i = 0; i < 8; i++)
                #pragma unroll
                for (int j = 0; j < 8; j++)
                    acc[i][j] += ar[i]*br[j];
        }
        __syncthreads();
    }

    float scale = (EPI == 2) ? *scale_p : 0.f;
    #pragma unroll
    for (int i = 0; i < 8; i++) {
        long r = bm*128 + tr*8 + i;
        #pragma unroll
        for (int j = 0; j < 8; j++) {
            int c = bn*128 + tc*8 + j;
            float v = acc[i][j];
            if (EPI == 0) v += bias[c];
            else if (EPI == 1) v = gelu_exact(v + bias[c]);
            else if (EPI == 2) v = resid[r*N + c] + scale*(v + bias[c]);
            C[r*(long)N + c] = v;
        }
    }
}

// ---------------- causal attention (flash-style, fp32) ----------------
// qkv layout: [B*S, 2304] with q/k/v at column offsets 0/768/1536, per head +h*64.
// output o: [B*S, 768] concat-head layout.
__global__ __launch_bounds__(64)
void attention_k(const float* __restrict__ qkv, float* __restrict__ o) {
    const int mt = blockIdx.x;          // query tile 0..15
    const int bh = blockIdx.y;          // 0..47
    const int b = bh / HH, h = bh % HH;
    const int tid = threadIdx.x;
    const int r = mt*64 + tid;          // query position in [0,1024)
    const float* base = qkv + (long)(b*SS)*QKVN + h*HSZ;

    float q[64];
    {
        const float4* qp = (const float4*)(base + (long)r*QKVN);
        #pragma unroll
        for (int i = 0; i < 16; i++) {
            float4 t = qp[i];
            q[4*i] = t.x; q[4*i+1] = t.y; q[4*i+2] = t.z; q[4*i+3] = t.w;
        }
    }

    __shared__ float ks[64][64];
    __shared__ float vs[64][64];
    float m_i = -1e30f, l_i = 0.f;
    float acc[64];
    #pragma unroll
    for (int e = 0; e < 64; e++) acc[e] = 0.f;

    const int lr = tid >> 4;            // 0..3
    const int lc = (tid & 15) * 4;      // 0..60

    for (int kt = 0; kt <= mt; kt++) {
        __syncthreads();
        #pragma unroll
        for (int p = 0; p < 16; p++) {
            int row = p*4 + lr;
            const float* kp = base + (long)(kt*64 + row)*QKVN + DD + lc;
            const float* vp = base + (long)(kt*64 + row)*QKVN + 2*DD + lc;
            *(float4*)&ks[row][lc] = *(const float4*)kp;
            *(float4*)&vs[row][lc] = *(const float4*)vp;
        }
        __syncthreads();
        int tmax = (kt == mt) ? (tid + 1) : 64;
        for (int t = 0; t < tmax; t++) {
            float s = 0.f;
            #pragma unroll
            for (int d4 = 0; d4 < 16; d4++) {
                float4 kk = *(const float4*)&ks[t][d4*4];
                s += q[d4*4]*kk.x + q[d4*4+1]*kk.y + q[d4*4+2]*kk.z + q[d4*4+3]*kk.w;
            }
            s *= INV_SQRT_HS;
            if (s > m_i) {
                float corr = __expf(m_i - s);
                m_i = s;
                l_i = l_i*corr + 1.f;
                #pragma unroll
                for (int e4 = 0; e4 < 16; e4++) {
                    float4 vv = *(const float4*)&vs[t][e4*4];
                    acc[e4*4  ] = acc[e4*4  ]*corr + vv.x;
                    acc[e4*4+1] = acc[e4*4+1]*corr + vv.y;
                    acc[e4*4+2] = acc[e4*4+2]*corr + vv.z;
                    acc[e4*4+3] = acc[e4*4+3]*corr + vv.w;
                }
            } else {
                float p = __expf(s - m_i);
                l_i += p;
                #pragma unroll
                for (int e4 = 0; e4 < 16; e4++) {
                    float4 vv = *(const float4*)&vs[t][e4*4];
                    acc[e4*4  ] += p*vv.x;
                    acc[e4*4+1] += p*vv.y;
                    acc[e4*4+2] += p*vv.z;
                    acc[e4*4+3] += p*vv.w;
                }
            }
        }
    }

    float inv = 1.f / l_i;
    float* op = o + (long)(b*SS + r)*DD + h*HSZ;
    #pragma unroll
    for (int e4 = 0; e4 < 16; e4++) {
        float4 w;
        w.x = acc[e4*4  ]*inv;
        w.y = acc[e4*4+1]*inv;
        w.z = acc[e4*4+2]*inv;
        w.w = acc[e4*4+3]*inv;
        *(float4*)(op + e4*4) = w;
    }
}

// ---------------- loss ----------------
__global__ void zero_loss_k() { g_loss_sum = 0.f; }

__global__ __launch_bounds__(256)
void loss_rows_k(const float* __restrict__ logits, const int* __restrict__ targets) {
    const int row = blockIdx.x;
    const int tid = threadIdx.x;
    const float* lr = logits + (long)row*VV;
    float m = -1e30f, l = 0.f;
    for (int c = tid; c < VV; c += 256) {
        float v = lr[c];
        if (v > m) { l = l*__expf(m - v) + 1.f; m = v; }
        else       { l += __expf(v - m); }
    }
    // combine (m,l) across warp
    #pragma unroll
    for (int off = 16; off > 0; off >>= 1) {
        float m2 = __shfl_xor_sync(0xffffffffu, m, off);
        float l2 = __shfl_xor_sync(0xffffffffu, l, off);
        float M = fmaxf(m, m2);
        l = l*__expf(m - M) + l2*__expf(m2 - M);
        m = M;
    }
    __shared__ float sm_m[8], sm_l[8];
    int warp = tid >> 5, lane = tid & 31;
    if (lane == 0) { sm_m[warp] = m; sm_l[warp] = l; }
    __syncthreads();
    if (tid < 32) {
        float mm = (lane < 8) ? sm_m[lane] : -1e30f;
        float ll = (lane < 8) ? sm_l[lane] : 0.f;
        #pragma unroll
        for (int off = 4; off > 0; off >>= 1) {
            float m2 = __shfl_xor_sync(0xffffffffu, mm, off);
            float l2 = __shfl_xor_sync(0xffffffffu, ll, off);
            float M = fmaxf(mm, m2);
            ll = ll*__expf(mm - M) + l2*__expf(m2 - M);
            mm = M;
        }
        if (lane == 0) {
            float lse = logf(ll) + mm;
            int tgt = targets[row];
            atomicAdd(&g_loss_sum, lse - lr[tgt]);
        }
    }
}

__global__ void finalize_loss_k(float* __restrict__ out) {
    out[0] = g_loss_sum * (1.0f / (float)MR);
}

// ---------------- launch ----------------
extern "C" void kernel_launch(void* const* d_in, const int* in_sizes, int n_in,
                              void* d_out, int out_size) {
    const int*   idx     = (const int*)  d_in[0];
    const int*   targets = (const int*)  d_in[1];
    const float* tok     = (const float*)d_in[2];
    const float* pos     = (const float*)d_in[3];
    const float* Wq      = (const float*)d_in[4];
    const float* bq      = (const float*)d_in[5];
    const float* Wk      = (const float*)d_in[6];
    const float* bk      = (const float*)d_in[7];
    const float* Wv      = (const float*)d_in[8];
    const float* bv      = (const float*)d_in[9];
    const float* Wo      = (const float*)d_in[10];
    const float* bo      = (const float*)d_in[11];
    const float* ln1g    = (const float*)d_in[12];
    const float* ln1b    = (const float*)d_in[13];
    const float* ln2g    = (const float*)d_in[14];
    const float* ln2b    = (const float*)d_in[15];
    const float* W1      = (const float*)d_in[16];
    const float* b1      = (const float*)d_in[17];
    const float* W2      = (const float*)d_in[18];
    const float* b2      = (const float*)d_in[19];
    const float* W3      = (const float*)d_in[20];
    const float* b3      = (const float*)d_in[21];
    const float* att_s   = (const float*)d_in[22];
    const float* ffd_s   = (const float*)d_in[23];
    const float* lnfg    = (const float*)d_in[24];
    const float* lnfb    = (const float*)d_in[25];
    float* out = (float*)d_out;

    float *x, *h, *qkv, *o, *f1, *f2, *Wp, *bp;
    cudaGetSymbolAddress((void**)&x,   g_x);
    cudaGetSymbolAddress((void**)&h,   g_h);
    cudaGetSymbolAddress((void**)&qkv, g_qkv);
    cudaGetSymbolAddress((void**)&o,   g_o);
    cudaGetSymbolAddress((void**)&f1,  g_f1);
    cudaGetSymbolAddress((void**)&f2,  g_f2);
    cudaGetSymbolAddress((void**)&Wp,  g_Wqkv);
    cudaGetSymbolAddress((void**)&bp,  g_bqkv);

    // pack qkv weights once per forward (deterministic; part of the graph)
    {
        long total = (long)LL*DD*QKVN;
        pack_qkv_w<<<(unsigned)((total + 255)/256), 256>>>(Wq, Wk, Wv, Wp);
        pack_qkv_b<<<(LL*QKVN + 255)/256, 256>>>(bq, bk, bv, bp);
    }

    embed_k<<<(MR*DD + 255)/256, 256>>>(idx, tok, pos, x);

    for (int l = 0; l < LL; l++) {
        layernorm_k<<<MR, 256>>>(x, h, ln1g + (long)l*DD, ln1b + (long)l*DD);
        sgemm_k<0,false><<<dim3(QKVN/128, MR/128), 256>>>(
            h, Wp + (long)l*DD*QKVN, bp + (long)l*QKVN, qkv, nullptr, nullptr,
            MR, QKVN, DD);
        attention_k<<<dim3(SS/64, BB*HH), 64>>>(qkv, o);
        sgemm_k<2,false><<<dim3(DD/128, MR/128), 256>>>(
            o, Wo + (long)l*DD*DD, bo + (long)l*DD, x, x, att_s + l,
            MR, DD, DD);
        layernorm_k<<<MR, 256>>>(x, h, ln2g + (long)l*DD, ln2b + (long)l*DD);
        sgemm_k<1,false><<<dim3(FF1/128, MR/128), 256>>>(
            h, W1 + (long)l*DD*FF1, b1 + (long)l*FF1, f1, nullptr, nullptr,
            MR, FF1, DD);
        sgemm_k<1,false><<<dim3(FF2/128, MR/128), 256>>>(
            f1, W2 + (long)l*FF1*FF2, b2 + (long)l*FF2, f2, nullptr, nullptr,
            MR, FF2, FF1);
        sgemm_k<2,false><<<dim3(DD/128, MR/128), 256>>>(
            f2, W3 + (long)l*FF2*DD, b3 + (long)l*DD, x, x, ffd_s + l,
            MR, DD, FF2);
    }

    layernorm_k<<<MR, 256>>>(x, h, lnfg, lnfb);

    // logits = h @ tok_emb^T  -> directly into d_out
    sgemm_k<3,true><<<dim3(VV/128, MR/128), 256>>>(
        h, tok, nullptr, out, nullptr, nullptr, MR, VV, DD);

    // loss
    zero_loss_k<<<1,1>>>();
    loss_rows_k<<<MR, 256>>>(out, targets);
    if (out_size > MR*(long)VV) {
        finalize_loss_k<<<1,1>>>(out + (long)MR*VV);
    }
}

// round 2
// speedup vs baseline: 2.2676x; 2.2676x over previous
#include <cuda_runtime.h>
#include <cuda_bf16.h>
#include <math.h>
#include <stdint.h>

// ---------------- problem constants ----------------
#define DD    768
#define SS    1024
#define BB    4
#define LL    12
#define HH    12
#define HSZ   64
#define VV    32000
#define MR    (BB*SS)        // 4096 rows
#define QKVN  (3*DD)         // 2304
#define FF1   (4*DD)         // 3072
#define FF2   (3*DD)         // 2304
#define INV_SQRT_D 0.03608439182435161f   // 1/sqrt(768)
#define INV_SQRT_HS 0.125f                // 1/sqrt(64)

// ---------------- scratch (device globals; no allocs) ----------------
__device__ float g_x   [MR*DD];
__device__ float g_h   [MR*DD];
__device__ float g_qkv [MR*QKVN];
__device__ float g_o   [MR*DD];
__device__ float g_f1  [MR*FF1];
__device__ float g_f2  [MR*FF2];
__device__ float g_Wqkv[LL*DD*QKVN];
__device__ float g_bqkv[LL*QKVN];
__device__ float g_loss_sum;

// ---------------- helpers ----------------
__device__ __forceinline__ float gelu_exact(float v) {
    return 0.5f * v * (1.0f + erff(v * 0.70710678118654752f));
}

__device__ __forceinline__ uint32_t f2tf(float x) {
    uint32_t r;
    asm("cvt.rna.tf32.f32 %0, %1;" : "=r"(r) : "f"(x));
    return r;
}

__device__ __forceinline__ void cp_async16(uint32_t dst, const void* src) {
    asm volatile("cp.async.cg.shared.global [%0], [%1], 16;\n" :: "r"(dst), "l"(src));
}
__device__ __forceinline__ void cp_commit() {
    asm volatile("cp.async.commit_group;\n" ::: "memory");
}

__device__ __forceinline__ void mma_tf32(float& d0, float& d1, float& d2, float& d3,
                                         uint32_t a0, uint32_t a1, uint32_t a2, uint32_t a3,
                                         uint32_t b0, uint32_t b1) {
    asm volatile(
        "mma.sync.aligned.m16n8k8.row.col.f32.tf32.tf32.f32 "
        "{%0,%1,%2,%3}, {%4,%5,%6,%7}, {%8,%9}, {%0,%1,%2,%3};\n"
        : "+f"(d0), "+f"(d1), "+f"(d2), "+f"(d3)
        : "r"(a0), "r"(a1), "r"(a2), "r"(a3), "r"(b0), "r"(b1));
}

// ---------------- weight packing: Wq/Wk/Wv -> [L][D][3*D] ----------------
__global__ void pack_qkv_w(const float* __restrict__ Wq, const float* __restrict__ Wk,
                           const float* __restrict__ Wv, float* __restrict__ Wp) {
    long i = (long)blockIdx.x * blockDim.x + threadIdx.x;
    long total = (long)LL * DD * QKVN;
    if (i >= total) return;
    int c = (int)(i % QKVN);
    long rem = i / QKVN;
    int d = (int)(rem % DD);
    int l = (int)(rem / DD);
    int which = c / DD;          // 0=q,1=k,2=v
    int ce = c % DD;
    int h = ce / HSZ;
    int e = ce % HSZ;
    const float* W = (which == 0) ? Wq : (which == 1) ? Wk : Wv;
    Wp[i] = W[(((long)l*HH + h)*DD + d)*HSZ + e];
}

__global__ void pack_qkv_b(const float* __restrict__ bq, const float* __restrict__ bk,
                           const float* __restrict__ bv, float* __restrict__ bp) {
    int i = blockIdx.x * blockDim.x + threadIdx.x;
    if (i >= LL*QKVN) return;
    int c = i % QKVN;
    int l = i / QKVN;
    int which = c / DD;
    int ce = c % DD;
    int h = ce / HSZ;
    int e = ce % HSZ;
    const float* b = (which == 0) ? bq : (which == 1) ? bk : bv;
    bp[i] = b[((long)l*HH + h)*HSZ + e];
}

// ---------------- embedding ----------------
__global__ void embed_k(const int* __restrict__ idx, const float* __restrict__ tok,
                        const float* __restrict__ pos, float* __restrict__ x) {
    long i = (long)blockIdx.x * blockDim.x + threadIdx.x;
    if (i >= (long)MR*DD) return;
    int d = (int)(i % DD);
    int r = (int)(i / DD);
    int s = r & (SS - 1);
    x[i] = tok[(long)idx[r]*DD + d] + pos[(long)s*DD + d] * INV_SQRT_D;
}

// ---------------- layernorm (one block per row) ----------------
__global__ __launch_bounds__(256)
void layernorm_k(const float* __restrict__ in, float* __restrict__ out,
                 const float* __restrict__ gamma, const float* __restrict__ beta) {
    int row = blockIdx.x;
    int tid = threadIdx.x;
    const float* xr = in + (long)row*DD;
    float v0 = xr[tid], v1 = xr[tid+256], v2 = xr[tid+512];
    float s = v0+v1+v2;
    float q = v0*v0 + v1*v1 + v2*v2;
    __shared__ float sm[16];
    #pragma unroll
    for (int off = 16; off > 0; off >>= 1) {
        s += __shfl_xor_sync(0xffffffffu, s, off);
        q += __shfl_xor_sync(0xffffffffu, q, off);
    }
    int warp = tid >> 5, lane = tid & 31;
    if (lane == 0) { sm[warp] = s; sm[warp+8] = q; }
    __syncthreads();
    if (tid < 32) {
        float ss = (lane < 8) ? sm[lane] : 0.f;
        float qq = (lane < 8) ? sm[lane+8] : 0.f;
        #pragma unroll
        for (int off = 4; off > 0; off >>= 1) {
            ss += __shfl_xor_sync(0xffffffffu, ss, off);
            qq += __shfl_xor_sync(0xffffffffu, qq, off);
        }
        if (lane == 0) {
            float mu = ss * (1.0f/768.0f);
            float var = qq * (1.0f/768.0f) - mu*mu;
            sm[0] = mu;
            sm[1] = rsqrtf(var + 1e-5f);
        }
    }
    __syncthreads();
    float mu = sm[0], rs = sm[1];
    float* orow = out + (long)row*DD;
    orow[tid    ] = (v0-mu)*rs*gamma[tid    ] + beta[tid    ];
    orow[tid+256] = (v1-mu)*rs*gamma[tid+256] + beta[tid+256];
    orow[tid+512] = (v2-mu)*rs*gamma[tid+512] + beta[tid+512];
}

// ---------------- tf32 tensor-core GEMM: 128x128 tile, 8 warps (32x64 each) ---
// EPI: 0 = +bias ; 1 = gelu(+bias) ; 2 = resid + scale*(acc+bias) ; 3 = plain
// TRB: B given as [N,K] row-major (compute A @ B^T)
template<int EPI, bool TRB>
__global__ __launch_bounds__(256)
void tgemm_k(const float* __restrict__ A, const float* __restrict__ Bm,
             const float* __restrict__ bias, float* __restrict__ C,
             const float* __restrict__ resid, const float* __restrict__ scale_p,
             int M, int N, int K) {
    // As[buf][m=128][k=16 pad->20]
    __shared__ float As[2*128*20];
    // non-TRB: Bs[buf][k=16][n=128 pad->136]; TRB: Bs[buf][n=128][k=16 pad->20]
    __shared__ float Bs[TRB ? (2*128*20) : (2*16*136)];

    const int tid  = threadIdx.x;
    const int bm   = blockIdx.y, bn = blockIdx.x;
    const int warp = tid >> 5, lane = tid & 31;
    const int wm   = warp >> 1, wn = warp & 1;     // 4x2 warp grid
    const int g    = lane >> 2, tg = lane & 3;

    // cp.async source/dst indices
    const int ar = tid >> 2;             // 0..63 (rows ar, ar+64)
    const int ac = (tid & 3) * 4;        // k-chunk
    const int bk = tid >> 5;             // 0..7 (k rows bk, bk+8) [non-TRB]
    const int bnb = (tid & 31) * 4;      // n-chunk [non-TRB]

    float acc[2][8][4];
    #pragma unroll
    for (int mi = 0; mi < 2; mi++)
        #pragma unroll
        for (int ni = 0; ni < 8; ni++)
            #pragma unroll
            for (int v = 0; v < 4; v++) acc[mi][ni][v] = 0.f;

    const int nsteps = K >> 4;

    auto issue = [&](int s, int buf) {
        int k0 = s << 4;
        #pragma unroll
        for (int p = 0; p < 2; p++) {
            int r = ar + p*64;
            uint32_t dst = (uint32_t)__cvta_generic_to_shared(&As[buf*2560 + r*20 + ac]);
            cp_async16(dst, A + (long)(bm*128 + r)*K + k0 + ac);
        }
        if (TRB) {
            #pragma unroll
            for (int p = 0; p < 2; p++) {
                int r = ar + p*64;
                uint32_t dst = (uint32_t)__cvta_generic_to_shared(&Bs[buf*2560 + r*20 + ac]);
                cp_async16(dst, Bm + (long)(bn*128 + r)*K + k0 + ac);
            }
        } else {
            #pragma unroll
            for (int p = 0; p < 2; p++) {
                int k = bk + p*8;
                uint32_t dst = (uint32_t)__cvta_generic_to_shared(&Bs[buf*2176 + k*136 + bnb]);
                cp_async16(dst, Bm + (long)(k0 + k)*N + bn*128 + bnb);
            }
        }
        cp_commit();
    };

    issue(0, 0);
    int buf = 0;
    for (int s = 0; s < nsteps; s++) {
        if (s + 1 < nsteps) {
            issue(s + 1, buf ^ 1);
            asm volatile("cp.async.wait_group 1;\n" ::: "memory");
        } else {
            asm volatile("cp.async.wait_group 0;\n" ::: "memory");
        }
        __syncthreads();

        const float* Ab = &As[buf*2560];
        const float* Bb = TRB ? &Bs[buf*2560] : &Bs[buf*2176];
        #pragma unroll
        for (int kc = 0; kc < 16; kc += 8) {
            uint32_t af[2][4];
            #pragma unroll
            for (int mi = 0; mi < 2; mi++) {
                int r0 = wm*32 + mi*16 + g;
                af[mi][0] = f2tf(Ab[(r0    )*20 + kc + tg    ]);
                af[mi][1] = f2tf(Ab[(r0 + 8)*20 + kc + tg    ]);
                af[mi][2] = f2tf(Ab[(r0    )*20 + kc + tg + 4]);
                af[mi][3] = f2tf(Ab[(r0 + 8)*20 + kc + tg + 4]);
            }
            uint32_t bf[8][2];
            #pragma unroll
            for (int ni = 0; ni < 8; ni++) {
                int n0 = wn*64 + ni*8 + g;
                if (TRB) {
                    bf[ni][0] = f2tf(Bb[n0*20 + kc + tg    ]);
                    bf[ni][1] = f2tf(Bb[n0*20 + kc + tg + 4]);
                } else {
                    bf[ni][0] = f2tf(Bb[(kc + tg    )*136 + n0]);
                    bf[ni][1] = f2tf(Bb[(kc + tg + 4)*136 + n0]);
                }
            }
            #pragma unroll
            for (int mi = 0; mi < 2; mi++)
                #pragma unroll
                for (int ni = 0; ni < 8; ni++)
                    mma_tf32(acc[mi][ni][0], acc[mi][ni][1], acc[mi][ni][2], acc[mi][ni][3],
                             af[mi][0], af[mi][1], af[mi][2], af[mi][3],
                             bf[ni][0], bf[ni][1]);
        }
        __syncthreads();
        buf ^= 1;
    }

    // ---------------- epilogue ----------------
    float scale = (EPI == 2) ? *scale_p : 0.f;
    #pragma unroll
    for (int mi = 0; mi < 2; mi++) {
        #pragma unroll
        for (int ni = 0; ni < 8; ni++) {
            int r0 = bm*128 + wm*32 + mi*16 + g;
            int c  = bn*128 + wn*64 + ni*8 + 2*tg;
            float2 bval = make_float2(0.f, 0.f);
            if (EPI == 0 || EPI == 1 || EPI == 2) bval = *(const float2*)(bias + c);
            #pragma unroll
            for (int half = 0; half < 2; half++) {
                long r = r0 + half*8;
                float v0 = acc[mi][ni][half*2    ];
                float v1 = acc[mi][ni][half*2 + 1];
                if (EPI == 0) { v0 += bval.x; v1 += bval.y; }
                else if (EPI == 1) { v0 = gelu_exact(v0 + bval.x); v1 = gelu_exact(v1 + bval.y); }
                else if (EPI == 2) {
                    float2 rv = *(const float2*)(resid + r*(long)N + c);
                    v0 = rv.x + scale*(v0 + bval.x);
                    v1 = rv.y + scale*(v1 + bval.y);
                }
                float2 w = make_float2(v0, v1);
                *(float2*)(C + r*(long)N + c) = w;
            }
        }
    }
}

// ---------------- causal attention (flash-style, fp32) ----------------
__global__ __launch_bounds__(64)
void attention_k(const float* __restrict__ qkv, float* __restrict__ o) {
    const int mt = blockIdx.x;          // query tile 0..15
    const int bh = blockIdx.y;          // 0..47
    const int b = bh / HH, h = bh % HH;
    const int tid = threadIdx.x;
    const int r = mt*64 + tid;          // query position in [0,1024)
    const float* base = qkv + (long)(b*SS)*QKVN + h*HSZ;

    float q[64];
    {
        const float4* qp = (const float4*)(base + (long)r*QKVN);
        #pragma unroll
        for (int i = 0; i < 16; i++) {
            float4 t = qp[i];
            q[4*i] = t.x; q[4*i+1] = t.y; q[4*i+2] = t.z; q[4*i+3] = t.w;
        }
    }

    __shared__ float ks[64][64];
    __shared__ float vs[64][64];
    float m_i = -1e30f, l_i = 0.f;
    float acc[64];
    #pragma unroll
    for (int e = 0; e < 64; e++) acc[e] = 0.f;

    const int lr = tid >> 4;            // 0..3
    const int lc = (tid & 15) * 4;      // 0..60

    for (int kt = 0; kt <= mt; kt++) {
        __syncthreads();
        #pragma unroll
        for (int p = 0; p < 16; p++) {
            int row = p*4 + lr;
            const float* kp = base + (long)(kt*64 + row)*QKVN + DD + lc;
            const float* vp = base + (long)(kt*64 + row)*QKVN + 2*DD + lc;
            *(float4*)&ks[row][lc] = *(const float4*)kp;
            *(float4*)&vs[row][lc] = *(const float4*)vp;
        }
        __syncthreads();
        int tmax = (kt == mt) ? (tid + 1) : 64;
        for (int t = 0; t < tmax; t++) {
            float s = 0.f;
            #pragma unroll
            for (int d4 = 0; d4 < 16; d4++) {
                float4 kk = *(const float4*)&ks[t][d4*4];
                s += q[d4*4]*kk.x + q[d4*4+1]*kk.y + q[d4*4+2]*kk.z + q[d4*4+3]*kk.w;
            }
            s *= INV_SQRT_HS;
            if (s > m_i) {
                float corr = __expf(m_i - s);
                m_i = s;
                l_i = l_i*corr + 1.f;
                #pragma unroll
                for (int e4 = 0; e4 < 16; e4++) {
                    float4 vv = *(const float4*)&vs[t][e4*4];
                    acc[e4*4  ] = acc[e4*4  ]*corr + vv.x;
                    acc[e4*4+1] = acc[e4*4+1]*corr + vv.y;
                    acc[e4*4+2] = acc[e4*4+2]*corr + vv.z;
                    acc[e4*4+3] = acc[e4*4+3]*corr + vv.w;
                }
            } else {
                float p = __expf(s - m_i);
                l_i += p;
                #pragma unroll
                for (int e4 = 0; e4 < 16; e4++) {
                    float4 vv = *(const float4*)&vs[t][e4*4];
                    acc[e4*4  ] += p*vv.x;
                    acc[e4*4+1] += p*vv.y;
                    acc[e4*4+2] += p*vv.z;
                    acc[e4*4+3] += p*vv.w;
                }
            }
        }
    }

    float inv = 1.f / l_i;
    float* op = o + (long)(b*SS + r)*DD + h*HSZ;
    #pragma unroll
    for (int e4 = 0; e4 < 16; e4++) {
        float4 w;
        w.x = acc[e4*4  ]*inv;
        w.y = acc[e4*4+1]*inv;
        w.z = acc[e4*4+2]*inv;
        w.w = acc[e4*4+3]*inv;
        *(float4*)(op + e4*4) = w;
    }
}

// ---------------- loss ----------------
__global__ void zero_loss_k() { g_loss_sum = 0.f; }

__global__ __launch_bounds__(256)
void loss_rows_k(const float* __restrict__ logits, const int* __restrict__ targets) {
    const int row = blockIdx.x;
    const int tid = threadIdx.x;
    const float* lr = logits + (long)row*VV;
    float m = -1e30f, l = 0.f;
    for (int c = tid; c < VV; c += 256) {
        float v = lr[c];
        if (v > m) { l = l*__expf(m - v) + 1.f; m = v; }
        else       { l += __expf(v - m); }
    }
    #pragma unroll
    for (int off = 16; off > 0; off >>= 1) {
        float m2 = __shfl_xor_sync(0xffffffffu, m, off);
        float l2 = __shfl_xor_sync(0xffffffffu, l, off);
        float M = fmaxf(m, m2);
        l = l*__expf(m - M) + l2*__expf(m2 - M);
        m = M;
    }
    __shared__ float sm_m[8], sm_l[8];
    int warp = tid >> 5, lane = tid & 31;
    if (lane == 0) { sm_m[warp] = m; sm_l[warp] = l; }
    __syncthreads();
    if (tid < 32) {
        float mm = (lane < 8) ? sm_m[lane] : -1e30f;
        float ll = (lane < 8) ? sm_l[lane] : 0.f;
        #pragma unroll
        for (int off = 4; off > 0; off >>= 1) {
            float m2 = __shfl_xor_sync(0xffffffffu, mm, off);
            float l2 = __shfl_xor_sync(0xffffffffu, ll, off);
            float M = fmaxf(mm, m2);
            ll = ll*__expf(mm - M) + l2*__expf(m2 - M);
            mm = M;
        }
        if (lane == 0) {
            float lse = logf(ll) + mm;
            int tgt = targets[row];
            atomicAdd(&g_loss_sum, lse - lr[tgt]);
        }
    }
}

__global__ void finalize_loss_k(float* __restrict__ out) {
    out[0] = g_loss_sum * (1.0f / (float)MR);
}

// ---------------- launch ----------------
extern "C" void kernel_launch(void* const* d_in, const int* in_sizes, int n_in,
                              void* d_out, int out_size) {
    const int*   idx     = (const int*)  d_in[0];
    const int*   targets = (const int*)  d_in[1];
    const float* tok     = (const float*)d_in[2];
    const float* pos     = (const float*)d_in[3];
    const float* Wq      = (const float*)d_in[4];
    const float* bq      = (const float*)d_in[5];
    const float* Wk      = (const float*)d_in[6];
    const float* bk      = (const float*)d_in[7];
    const float* Wv      = (const float*)d_in[8];
    const float* bv      = (const float*)d_in[9];
    const float* Wo      = (const float*)d_in[10];
    const float* bo      = (const float*)d_in[11];
    const float* ln1g    = (const float*)d_in[12];
    const float* ln1b    = (const float*)d_in[13];
    const float* ln2g    = (const float*)d_in[14];
    const float* ln2b    = (const float*)d_in[15];
    const float* W1      = (const float*)d_in[16];
    const float* b1      = (const float*)d_in[17];
    const float* W2      = (const float*)d_in[18];
    const float* b2      = (const float*)d_in[19];
    const float* W3      = (const float*)d_in[20];
    const float* b3      = (const float*)d_in[21];
    const float* att_s   = (const float*)d_in[22];
    const float* ffd_s   = (const float*)d_in[23];
    const float* lnfg    = (const float*)d_in[24];
    const float* lnfb    = (const float*)d_in[25];
    float* out = (float*)d_out;

    float *x, *h, *qkv, *o, *f1, *f2, *Wp, *bp;
    cudaGetSymbolAddress((void**)&x,   g_x);
    cudaGetSymbolAddress((void**)&h,   g_h);
    cudaGetSymbolAddress((void**)&qkv, g_qkv);
    cudaGetSymbolAddress((void**)&o,   g_o);
    cudaGetSymbolAddress((void**)&f1,  g_f1);
    cudaGetSymbolAddress((void**)&f2,  g_f2);
    cudaGetSymbolAddress((void**)&Wp,  g_Wqkv);
    cudaGetSymbolAddress((void**)&bp,  g_bqkv);

    {
        long total = (long)LL*DD*QKVN;
        pack_qkv_w<<<(unsigned)((total + 255)/256), 256>>>(Wq, Wk, Wv, Wp);
        pack_qkv_b<<<(LL*QKVN + 255)/256, 256>>>(bq, bk, bv, bp);
    }

    embed_k<<<(MR*DD + 255)/256, 256>>>(idx, tok, pos, x);

    for (int l = 0; l < LL; l++) {
        layernorm_k<<<MR, 256>>>(x, h, ln1g + (long)l*DD, ln1b + (long)l*DD);
        tgemm_k<0,false><<<dim3(QKVN/128, MR/128), 256>>>(
            h, Wp + (long)l*DD*QKVN, bp + (long)l*QKVN, qkv, nullptr, nullptr,
            MR, QKVN, DD);
        attention_k<<<dim3(SS/64, BB*HH), 64>>>(qkv, o);
        tgemm_k<2,false><<<dim3(DD/128, MR/128), 256>>>(
            o, Wo + (long)l*DD*DD, bo + (long)l*DD, x, x, att_s + l,
            MR, DD, DD);
        layernorm_k<<<MR, 256>>>(x, h, ln2g + (long)l*DD, ln2b + (long)l*DD);
        tgemm_k<1,false><<<dim3(FF1/128, MR/128), 256>>>(
            h, W1 + (long)l*DD*FF1, b1 + (long)l*FF1, f1, nullptr, nullptr,
            MR, FF1, DD);
        tgemm_k<1,false><<<dim3(FF2/128, MR/128), 256>>>(
            f1, W2 + (long)l*FF1*FF2, b2 + (long)l*FF2, f2, nullptr, nullptr,
            MR, FF2, FF1);
        tgemm_k<2,false><<<dim3(DD/128, MR/128), 256>>>(
            f2, W3 + (long)l*FF2*DD, b3 + (long)l*DD, x, x, ffd_s + l,
            MR, DD, FF2);
    }

    layernorm_k<<<MR, 256>>>(x, h, lnfg, lnfb);

    // logits = h @ tok_emb^T  -> directly into d_out
    tgemm_k<3,true><<<dim3(VV/128, MR/128), 256>>>(
        h, tok, nullptr, out, nullptr, nullptr, MR, VV, DD);

    // loss
    zero_loss_k<<<1,1>>>();
    loss_rows_k<<<MR, 256>>>(out, targets);
    if (out_size > MR*(long)VV) {
        finalize_loss_k<<<1,1>>>(out + (long)MR*VV);
    }
}